// round 2
// baseline (speedup 1.0000x reference)
#include <cuda_runtime.h>
#include <cuda_fp16.h>
#include <cstdint>

// ======================= problem constants =======================
static constexpr int K_DIM  = 2048;   // fan-in
static constexpr int N_ROWS = 8192;   // weight rows (proj width)
static constexpr int M_TOK  = 8192;   // tokens
static constexpr int N_OUT  = 4096;   // output cols after GLU

// ======================= GEMM tiling =============================
static constexpr int BM = 128;        // token rows per CTA
static constexpr int BR = 128;        // B rows per CTA = 64 h + 64 g
static constexpr int BK = 64;         // K per stage
static constexpr int NCHUNK = K_DIM / BK;   // 32
static constexpr int NSTAGE = 3;
static constexpr int TILE_BYTES  = BM * BK * 2;        // 16384
static constexpr int STAGE_BYTES = 2 * TILE_BYTES;     // A + B = 32768
static constexpr int SMEM_TOTAL  = NSTAGE * STAGE_BYTES;  // 98304

// ======================= device scratch ==========================
__device__ float  g55_partial[2048];
__device__ float  g55_wgamma;
__device__ __half g55_wbin[(size_t)N_ROWS * K_DIM];   // ternary weights fp16, K-major
__device__ __half g55_act [(size_t)M_TOK  * K_DIM];   // layernormed x fp16, K-major

struct __align__(16) H8 { __half2 a, b, c, d; };

// ======================= asm helpers =============================
__device__ __forceinline__ uint32_t smem_u32(const void* p) {
    uint32_t a;
    asm("{ .reg .u64 t; cvta.to.shared.u64 t, %1; cvt.u32.u64 %0, t; }" : "=r"(a) : "l"(p));
    return a;
}

#define CP_ASYNC16(dst_u32, src_ptr) \
    asm volatile("cp.async.cg.shared.global [%0], [%1], 16;" \
                 :: "r"(dst_u32), "l"(src_ptr) : "memory")

#define CP_COMMIT() asm volatile("cp.async.commit_group;" ::: "memory")
#define CP_WAIT(n)  asm volatile("cp.async.wait_group %0;" :: "n"(n) : "memory")

#define LDSM_X4(r0, r1, r2, r3, addr) \
    asm volatile("ldmatrix.sync.aligned.m8n8.x4.shared.b16 {%0,%1,%2,%3}, [%4];" \
                 : "=r"(r0), "=r"(r1), "=r"(r2), "=r"(r3) : "r"(addr))

#define MMA16816(d, a0, a1, a2, a3, b0, b1) \
    asm volatile("mma.sync.aligned.m16n8k16.row.col.f32.f16.f16.f32 " \
                 "{%0,%1,%2,%3}, {%4,%5,%6,%7}, {%8,%9}, {%0,%1,%2,%3};" \
                 : "+f"((d)[0]), "+f"((d)[1]), "+f"((d)[2]), "+f"((d)[3]) \
                 : "r"(a0), "r"(a1), "r"(a2), "r"(a3), "r"(b0), "r"(b1))

__device__ __forceinline__ float warp_sum(float v) {
#pragma unroll
    for (int o = 16; o; o >>= 1) v += __shfl_xor_sync(0xffffffffu, v, o);
    return v;
}

// ======================= prep kernels ============================

__global__ __launch_bounds__(256) void glu55_wabs_partial(const float* __restrict__ w) {
    const int tid = threadIdx.x;
    const float4* w4 = reinterpret_cast<const float4*>(w);
    float s = 0.0f;
    int idx = blockIdx.x * 256 + tid;
#pragma unroll
    for (int i = 0; i < 8; ++i) {
        float4 v = w4[idx + i * (2048 * 256)];
        s += fabsf(v.x) + fabsf(v.y) + fabsf(v.z) + fabsf(v.w);
    }
    s = warp_sum(s);
    __shared__ float sh[8];
    if ((tid & 31) == 0) sh[tid >> 5] = s;
    __syncthreads();
    if (tid == 0) {
        float t = 0.0f;
#pragma unroll
        for (int i = 0; i < 8; ++i) t += sh[i];
        g55_partial[blockIdx.x] = t;
    }
}

__global__ __launch_bounds__(256) void glu55_wabs_final() {
    const int tid = threadIdx.x;
    float s = 0.0f;
    for (int i = tid; i < 2048; i += 256) s += g55_partial[i];
    s = warp_sum(s);
    __shared__ float sh[8];
    if ((tid & 31) == 0) sh[tid >> 5] = s;
    __syncthreads();
    if (tid == 0) {
        float t = 0.0f;
#pragma unroll
        for (int i = 0; i < 8; ++i) t += sh[i];
        g55_wgamma = t / (float)((size_t)N_ROWS * K_DIM);
    }
}

__device__ __forceinline__ float tern1(float v, float inv) {
    float r = rintf(v * inv);                 // round-half-even = jnp.round
    return fminf(1.0f, fmaxf(-1.0f, r));
}

__global__ __launch_bounds__(256) void glu55_tern(const float* __restrict__ w) {
    const int gid = blockIdx.x * 256 + threadIdx.x;
    const float inv = 1.0f / (g55_wgamma + 1e-7f);
    const float4* w4 = reinterpret_cast<const float4*>(w);
    float4 a = w4[gid * 2 + 0];
    float4 b = w4[gid * 2 + 1];
    H8 o;
    o.a = __floats2half2_rn(tern1(a.x, inv), tern1(a.y, inv));
    o.b = __floats2half2_rn(tern1(a.z, inv), tern1(a.w, inv));
    o.c = __floats2half2_rn(tern1(b.x, inv), tern1(b.y, inv));
    o.d = __floats2half2_rn(tern1(b.z, inv), tern1(b.w, inv));
    reinterpret_cast<H8*>(g55_wbin)[gid] = o;
}

__global__ __launch_bounds__(256) void glu55_ln(const float* __restrict__ x) {
    const int row = blockIdx.x;
    const int tid = threadIdx.x;
    const float4* xr = reinterpret_cast<const float4*>(x + (size_t)row * K_DIM);
    float4 v0 = xr[tid * 2 + 0];
    float4 v1 = xr[tid * 2 + 1];
    float s = v0.x + v0.y + v0.z + v0.w + v1.x + v1.y + v1.z + v1.w;
    float q = v0.x * v0.x + v0.y * v0.y + v0.z * v0.z + v0.w * v0.w +
              v1.x * v1.x + v1.y * v1.y + v1.z * v1.z + v1.w * v1.w;
    s = warp_sum(s);
    q = warp_sum(q);
    __shared__ float sh[18];
    const int wid = tid >> 5, lid = tid & 31;
    if (lid == 0) { sh[wid] = s; sh[8 + wid] = q; }
    __syncthreads();
    if (tid == 0) {
        float S = 0.0f, Q = 0.0f;
#pragma unroll
        for (int i = 0; i < 8; ++i) { S += sh[i]; Q += sh[8 + i]; }
        float mu  = S * (1.0f / (float)K_DIM);
        float var = Q * (1.0f / (float)K_DIM) - mu * mu;
        sh[16] = mu;
        sh[17] = rsqrtf(var + 1e-5f);
    }
    __syncthreads();
    const float mu = sh[16], rs = sh[17];
    H8 o;
    o.a = __floats2half2_rn((v0.x - mu) * rs, (v0.y - mu) * rs);
    o.b = __floats2half2_rn((v0.z - mu) * rs, (v0.w - mu) * rs);
    o.c = __floats2half2_rn((v1.x - mu) * rs, (v1.y - mu) * rs);
    o.d = __floats2half2_rn((v1.z - mu) * rs, (v1.w - mu) * rs);
    reinterpret_cast<H8*>(g55_act)[(size_t)row * (K_DIM / 8) + tid] = o;
}

// ======================= GEMM + fused GLU ========================
// 8 warps: wm = wid&3 (m offset wm*32), ngrp = wid>>2 (n offset ngrp*32).
// B smem tile rows: 0..63 = h weight rows (out cols nTile*64..+63),
//                  64..127 = g weight rows (same out cols, +4096 in W).
// Each warp holds matching h and g accum frags -> GLU fused in registers.

__global__ void __launch_bounds__(256, 2) glu55_gemm(
    const __half* __restrict__ A, const __half* __restrict__ B,
    float* __restrict__ out)
{
    extern __shared__ char smem[];
    const uint32_t sbase = smem_u32(smem);
    const int tid  = threadIdx.x;
    const int lane = tid & 31;
    const int wid  = tid >> 5;
    const int wm   = wid & 3;
    const int ngrp = wid >> 2;
    const int mTile = blockIdx.x & 63;
    const int nTile = blockIdx.x >> 6;

    const __half* gA = A + (size_t)mTile * BM * K_DIM;

    float ah[2][4][4], ag[2][4][4];
#pragma unroll
    for (int i = 0; i < 2; ++i)
#pragma unroll
        for (int j = 0; j < 4; ++j)
#pragma unroll
            for (int k = 0; k < 4; ++k) { ah[i][j][k] = 0.0f; ag[i][j][k] = 0.0f; }

    // precomputed per-thread load indices
    const int ld_row = tid >> 3;        // 0..31 (per 256-thread pass)
    const int ld_ch  = tid & 7;

    auto issue_stage = [&](int st, int c) {
        const int k0 = c * BK;
        const uint32_t sA = sbase + st * STAGE_BYTES;
        const uint32_t sB = sA + TILE_BYTES;
#pragma unroll
        for (int it = 0; it < 4; ++it) {
            const int row = it * 32 + ld_row;
            const __half* src = gA + (size_t)row * K_DIM + k0 + ld_ch * 8;
            const uint32_t dst = sA + row * 128 + ((ld_ch ^ (row & 7)) << 4);
            CP_ASYNC16(dst, src);
        }
#pragma unroll
        for (int it = 0; it < 4; ++it) {
            const int row = it * 32 + ld_row;
            const int grow = nTile * 64 + (row & 63) + ((row >> 6) << 12); // +4096 for g half
            const __half* src = B + (size_t)grow * K_DIM + k0 + ld_ch * 8;
            const uint32_t dst = sB + row * 128 + ((ld_ch ^ (row & 7)) << 4);
            CP_ASYNC16(dst, src);
        }
        CP_COMMIT();
    };

    auto compute_stage = [&](int st) {
        const uint32_t sA = sbase + st * STAGE_BYTES;
        const uint32_t sB = sA + TILE_BYTES;
#pragma unroll
        for (int kk = 0; kk < 4; ++kk) {
            uint32_t a[2][4];
#pragma unroll
            for (int mt = 0; mt < 2; ++mt) {
                const int row = wm * 32 + mt * 16 + (lane & 15);
                const int ch  = kk * 2 + (lane >> 4);
                const uint32_t addr = sA + row * 128 + ((ch ^ (row & 7)) << 4);
                LDSM_X4(a[mt][0], a[mt][1], a[mt][2], a[mt][3], addr);
            }
            uint32_t bh[2][4], bg[2][4];
#pragma unroll
            for (int tp = 0; tp < 2; ++tp) {
                const int rb = ngrp * 32 + tp * 16 + ((lane >> 4) << 3) + (lane & 7);
                const int ch = kk * 2 + ((lane >> 3) & 1);
                const uint32_t sw = ((ch ^ (rb & 7)) << 4);
                LDSM_X4(bh[tp][0], bh[tp][1], bh[tp][2], bh[tp][3], sB + rb * 128 + sw);
                LDSM_X4(bg[tp][0], bg[tp][1], bg[tp][2], bg[tp][3], sB + (rb + 64) * 128 + sw);
            }
#pragma unroll
            for (int mt = 0; mt < 2; ++mt)
#pragma unroll
                for (int tp = 0; tp < 2; ++tp) {
                    MMA16816(ah[mt][2 * tp + 0], a[mt][0], a[mt][1], a[mt][2], a[mt][3], bh[tp][0], bh[tp][1]);
                    MMA16816(ah[mt][2 * tp + 1], a[mt][0], a[mt][1], a[mt][2], a[mt][3], bh[tp][2], bh[tp][3]);
                    MMA16816(ag[mt][2 * tp + 0], a[mt][0], a[mt][1], a[mt][2], a[mt][3], bg[tp][0], bg[tp][1]);
                    MMA16816(ag[mt][2 * tp + 1], a[mt][0], a[mt][1], a[mt][2], a[mt][3], bg[tp][2], bg[tp][3]);
                }
        }
    };

    issue_stage(0, 0);
    issue_stage(1, 1);

    int st = 0;
    for (int c = 0; c < NCHUNK; ++c) {
        CP_WAIT(1);
        __syncthreads();
        compute_stage(st);
        if (c + 2 < NCHUNK) {
            int st2 = st + 2; if (st2 >= NSTAGE) st2 -= NSTAGE;
            issue_stage(st2, c + 2);
        } else {
            CP_COMMIT();   // keep group counting aligned
        }
        if (++st == NSTAGE) st = 0;
    }

    // ---- fused GLU epilogue (all in registers) ----
    const float gw = g55_wgamma;
    const int row0 = mTile * BM + wm * 32 + (lane >> 2);
    const int col0 = nTile * 64 + ngrp * 32 + 2 * (lane & 3);
#pragma unroll
    for (int mt = 0; mt < 2; ++mt)
#pragma unroll
        for (int nt = 0; nt < 4; ++nt)
#pragma unroll
            for (int hf = 0; hf < 2; ++hf) {
                const float h0 = ah[mt][nt][2 * hf + 0] * gw;
                const float h1 = ah[mt][nt][2 * hf + 1] * gw;
                const float g0 = ag[mt][nt][2 * hf + 0] * gw;
                const float g1 = ag[mt][nt][2 * hf + 1] * gw;
                float2 o;
                o.x = h0 * (g0 / (1.0f + __expf(-g0)));
                o.y = h1 * (g1 / (1.0f + __expf(-g1)));
                const int r = row0 + mt * 16 + hf * 8;
                *reinterpret_cast<float2*>(out + (size_t)r * N_OUT + col0 + nt * 8) = o;
            }
}

// ======================= host launcher ===========================

extern "C" void kernel_launch(void* const* d_in, const int* in_sizes, int n_in,
                              void* d_out, int out_size) {
    (void)in_sizes; (void)n_in; (void)out_size;
    const float* x = (const float*)d_in[0];
    const float* w = (const float*)d_in[1];
    float* out = (float*)d_out;

    void *p_wbin = nullptr, *p_act = nullptr;
    cudaGetSymbolAddress(&p_wbin, g55_wbin);
    cudaGetSymbolAddress(&p_act,  g55_act);

    glu55_wabs_partial<<<2048, 256>>>(w);
    glu55_wabs_final<<<1, 256>>>();
    glu55_tern<<<8192, 256>>>(w);
    glu55_ln<<<M_TOK, 256>>>(x);

    static bool attr_done = false;
    if (!attr_done) {
        cudaFuncSetAttribute(glu55_gemm, cudaFuncAttributeMaxDynamicSharedMemorySize, SMEM_TOTAL);
        attr_done = true;
    }
    glu55_gemm<<<(M_TOK / BM) * (N_OUT / 64), 256, SMEM_TOTAL>>>(
        (const __half*)p_act, (const __half*)p_wbin, out);
}